// round 9
// baseline (speedup 1.0000x reference)
#include <cuda_runtime.h>
#include <cstdint>

#define N_NODES 50000
#define CDIM 128
#define XDIM 384
#define E_MAX 1000000

// ---------------------------------------------------------------------------
// scratch (__device__ globals; no allocation allowed)
// ---------------------------------------------------------------------------
__device__ float g_h0[N_NODES * CDIM];
__device__ float g_agg[N_NODES * CDIM];
__device__ float g_h1[N_NODES * CDIM];
__device__ int   g_cnt[N_NODES];
__device__ int   g_rowptr[N_NODES + 1];
__device__ int   g_cursor[N_NODES];
__device__ int   g_esrc[E_MAX];

// tf32-split weights, SAME layout as input W ([K,128], k-major):
#define WT_OFF_LIN 0
#define WT_OFF_1L  (XDIM * CDIM)
#define WT_OFF_1R  (WT_OFF_1L + CDIM * CDIM)
#define WT_OFF_2L  (WT_OFF_1R + CDIM * CDIM)
#define WT_OFF_2R  (WT_OFF_2L + CDIM * CDIM)
#define WT_TOTAL   (WT_OFF_2R + CDIM * CDIM)
__device__ float g_wt_hi[WT_TOTAL];
__device__ float g_wt_lo[WT_TOTAL];

// ---------------------------------------------------------------------------
// helpers
// ---------------------------------------------------------------------------
__device__ __forceinline__ float tf32_rna(float x) {
    uint32_t u;
    asm("cvt.rna.tf32.f32 %0, %1;" : "=r"(u) : "f"(x));
    return __uint_as_float(u);
}

__device__ __forceinline__ uint32_t smem_u32(const void* p) {
    uint32_t a;
    asm("{ .reg .u64 t; cvta.to.shared.u64 t, %1; cvt.u32.u64 %0, t; }" : "=r"(a) : "l"(p));
    return a;
}

__device__ __forceinline__ void cp_async16(uint32_t smem_addr, const void* gptr) {
    asm volatile("cp.async.cg.shared.global [%0], [%1], 16;" :: "r"(smem_addr), "l"(gptr));
}
#define CP_COMMIT() asm volatile("cp.async.commit_group;" ::: "memory")
#define CP_WAIT(n)  asm volatile("cp.async.wait_group %0;" :: "n"(n) : "memory")

__device__ __forceinline__ void mma_tf32(float* d,
                                         uint32_t a0, uint32_t a1, uint32_t a2, uint32_t a3,
                                         uint32_t b0, uint32_t b1) {
    asm volatile(
        "mma.sync.aligned.m16n8k8.row.col.f32.tf32.tf32.f32 "
        "{%0,%1,%2,%3}, {%4,%5,%6,%7}, {%8,%9}, {%0,%1,%2,%3};"
        : "+f"(d[0]), "+f"(d[1]), "+f"(d[2]), "+f"(d[3])
        : "r"(a0), "r"(a1), "r"(a2), "r"(a3), "r"(b0), "r"(b1));
}

// ---------------------------------------------------------------------------
// CSR build
// ---------------------------------------------------------------------------
__global__ void hist_kernel(const int* __restrict__ dst, int* __restrict__ cnt, int E) {
    int i = blockIdx.x * blockDim.x + threadIdx.x;
    int stride = gridDim.x * blockDim.x;
    for (; i < E; i += stride) atomicAdd(&cnt[dst[i]], 1);
}

__global__ void scan_kernel(const int* __restrict__ cnt, int* __restrict__ rowptr,
                            int* __restrict__ cursor, int n) {
    __shared__ int wsum[32];
    __shared__ int carry;
    int tid = threadIdx.x, lane = tid & 31, wid = tid >> 5;
    if (tid == 0) carry = 0;
    __syncthreads();
    for (int base = 0; base < n; base += 1024) {
        int idx = base + tid;
        int v = (idx < n) ? cnt[idx] : 0;
        int x = v;
#pragma unroll
        for (int off = 1; off < 32; off <<= 1) {
            int t = __shfl_up_sync(0xffffffffu, x, off);
            if (lane >= off) x += t;
        }
        if (lane == 31) wsum[wid] = x;
        __syncthreads();
        if (wid == 0) {
            int w = wsum[lane];
#pragma unroll
            for (int off = 1; off < 32; off <<= 1) {
                int t = __shfl_up_sync(0xffffffffu, w, off);
                if (lane >= off) w += t;
            }
            wsum[lane] = w;
        }
        __syncthreads();
        int incl = x + (wid ? wsum[wid - 1] : 0);
        int excl = incl - v + carry;
        if (idx < n) { rowptr[idx] = excl; cursor[idx] = excl; }
        int chunk_total = wsum[31];
        __syncthreads();
        if (tid == 0) carry += chunk_total;
        __syncthreads();
    }
    if (tid == 0) rowptr[n] = carry;
}

__global__ void fill_kernel(const int* __restrict__ src, const int* __restrict__ dst,
                            int* __restrict__ cursor, int* __restrict__ esrc, int E) {
    int i = blockIdx.x * blockDim.x + threadIdx.x;
    int stride = gridDim.x * blockDim.x;
    for (; i < E; i += stride) {
        int d = dst[i];
        int pos = atomicAdd(&cursor[d], 1);
        esrc[pos] = src[i];
    }
}

// ---------------------------------------------------------------------------
// aggregate (mean of in-neighbors): one warp per node, 4-deep unroll
// ---------------------------------------------------------------------------
__global__ void aggregate_kernel(const float* __restrict__ h,
                                 const int* __restrict__ rowptr,
                                 const int* __restrict__ esrc,
                                 float* __restrict__ agg, int M) {
    int warp = (blockIdx.x * blockDim.x + threadIdx.x) >> 5;
    int lane = threadIdx.x & 31;
    if (warp >= M) return;
    int beg = rowptr[warp];
    int end = rowptr[warp + 1];
    float4 a0 = make_float4(0.f, 0.f, 0.f, 0.f);
    float4 a1 = make_float4(0.f, 0.f, 0.f, 0.f);
    float4 a2 = make_float4(0.f, 0.f, 0.f, 0.f);
    float4 a3 = make_float4(0.f, 0.f, 0.f, 0.f);
    int i = beg;
    for (; i + 3 < end; i += 4) {
        int s0 = esrc[i], s1 = esrc[i + 1], s2 = esrc[i + 2], s3 = esrc[i + 3];
        float4 v0 = ((const float4*)(h + (size_t)s0 * CDIM))[lane];
        float4 v1 = ((const float4*)(h + (size_t)s1 * CDIM))[lane];
        float4 v2 = ((const float4*)(h + (size_t)s2 * CDIM))[lane];
        float4 v3 = ((const float4*)(h + (size_t)s3 * CDIM))[lane];
        a0.x += v0.x; a0.y += v0.y; a0.z += v0.z; a0.w += v0.w;
        a1.x += v1.x; a1.y += v1.y; a1.z += v1.z; a1.w += v1.w;
        a2.x += v2.x; a2.y += v2.y; a2.z += v2.z; a2.w += v2.w;
        a3.x += v3.x; a3.y += v3.y; a3.z += v3.z; a3.w += v3.w;
    }
    for (; i < end; i++) {
        int s0 = esrc[i];
        float4 v0 = ((const float4*)(h + (size_t)s0 * CDIM))[lane];
        a0.x += v0.x; a0.y += v0.y; a0.z += v0.z; a0.w += v0.w;
    }
    float inv = 1.0f / fmaxf((float)(end - beg), 1.0f);
    float4 r;
    r.x = (a0.x + a1.x + a2.x + a3.x) * inv;
    r.y = (a0.y + a1.y + a2.y + a3.y) * inv;
    r.z = (a0.z + a1.z + a2.z + a3.z) * inv;
    r.w = (a0.w + a1.w + a2.w + a3.w) * inv;
    ((float4*)(agg + (size_t)warp * CDIM))[lane] = r;
}

// ---------------------------------------------------------------------------
// weight split (all 5 matrices, one launch)
// ---------------------------------------------------------------------------
__global__ void wsplit_all_kernel(const float* __restrict__ Wlin,
                                  const float* __restrict__ W1l,
                                  const float* __restrict__ W1r,
                                  const float* __restrict__ W2l,
                                  const float* __restrict__ W2r,
                                  float* __restrict__ Th, float* __restrict__ Tl) {
    int idx = blockIdx.x * blockDim.x + threadIdx.x;
    if (idx >= WT_TOTAL) return;
    float w;
    if (idx < WT_OFF_1L)      w = Wlin[idx];
    else if (idx < WT_OFF_1R) w = W1l[idx - WT_OFF_1L];
    else if (idx < WT_OFF_2L) w = W1r[idx - WT_OFF_1R];
    else if (idx < WT_OFF_2R) w = W2l[idx - WT_OFF_2L];
    else                      w = W2r[idx - WT_OFF_2R];
    float h = tf32_rna(w);
    float l = tf32_rna(w - h);
    Th[idx] = h;
    Tl[idx] = l;
}

// ---------------------------------------------------------------------------
// 3xTF32 mma.sync GEMM, cp.async double-buffered B + register-prefetched A:
//   out[M,128] = A1[M,K1] @ B1[K1,128] + A2[M,K2] @ B2[K2,128] + bias (opt relu)
// ---------------------------------------------------------------------------
#define SA_PAD 36
#define SB_PAD 136
#define SA_ELEMS (128 * SA_PAD)
#define SB_ELEMS (32 * SB_PAD)
#define GEMM_SMEM ((2 * SA_ELEMS + 4 * SB_ELEMS) * 4)  // 106496 B

__global__ __launch_bounds__(256, 2)
void gemm3t_kernel(const float* __restrict__ A1, int K1,
                   const float* __restrict__ A2, int K2,
                   const float* __restrict__ B1h, const float* __restrict__ B1l,
                   const float* __restrict__ B2h, const float* __restrict__ B2l,
                   const float* __restrict__ bias,
                   float* __restrict__ out, int M, int do_relu) {
    extern __shared__ float smf[];
    float* sAh = smf;
    float* sAl = smf + SA_ELEMS;
    float* sB  = smf + 2 * SA_ELEMS;

    int tid = threadIdx.x;
    int wid = tid >> 5;
    int lane = tid & 31;
    int gi = lane >> 2;
    int tg = lane & 3;
    int wm = wid & 3;
    int wn = wid >> 2;
    int row0 = blockIdx.x * 128;

    float acc[2][8][4];
#pragma unroll
    for (int mt = 0; mt < 2; mt++)
#pragma unroll
        for (int nt = 0; nt < 8; nt++)
#pragma unroll
            for (int r = 0; r < 4; r++) acc[mt][nt][r] = 0.f;

    int nChunks = (K1 + K2) >> 5;
    int trow = tid >> 1;
    int arow = row0 + trow;

    auto issue_B = [&](int c, int buf) {
        int gk = c << 5;
        const float* Bh; const float* Bl; int kb;
        if (gk < K1) { Bh = B1h; Bl = B1l; kb = gk; }
        else         { Bh = B2h; Bl = B2l; kb = gk - K1; }
        float* dsth = sB + buf * 2 * SB_ELEMS;
        float* dstl = dsth + SB_ELEMS;
#pragma unroll
        for (int t = 0; t < 4; t++) {
            int idx = tid + t * 256;
            int kk = idx >> 5;
            int c4 = idx & 31;
            size_t goff = (size_t)(kb + kk) * CDIM + c4 * 4;
            int soff = kk * SB_PAD + c4 * 4;
            cp_async16(smem_u32(dsth + soff), Bh + goff);
            cp_async16(smem_u32(dstl + soff), Bl + goff);
        }
        CP_COMMIT();
    };

    auto load_A = [&](int c, float4* v) {
        int gk = c << 5;
        const float* Asrc; int lda; int kb;
        if (gk < K1) { Asrc = A1; lda = K1; kb = gk; }
        else         { Asrc = A2; lda = K2; kb = gk - K1; }
        if (arow < M) {
            const float* ap = Asrc + (size_t)arow * lda + kb;
#pragma unroll
            for (int j = 0; j < 4; j++) {
                int q = (j << 1) | (tid & 1);
                v[j] = *(const float4*)(ap + q * 4);
            }
        } else {
            float4 z = make_float4(0.f, 0.f, 0.f, 0.f);
#pragma unroll
            for (int j = 0; j < 4; j++) v[j] = z;
        }
    };

    // prologue: stage B(0), prefetch A(0) into regs
    issue_B(0, 0);
    float4 va[4], vb[4];
    load_A(0, va);

    for (int c = 0; c < nChunks; c++) {
        int buf = c & 1;

        // split+store A(c) from prefetched regs
#pragma unroll
        for (int j = 0; j < 4; j++) {
            int q = (j << 1) | (tid & 1);
            float4 v = va[j];
            float4 h, l;
            h.x = tf32_rna(v.x); l.x = tf32_rna(v.x - h.x);
            h.y = tf32_rna(v.y); l.y = tf32_rna(v.y - h.y);
            h.z = tf32_rna(v.z); l.z = tf32_rna(v.z - h.z);
            h.w = tf32_rna(v.w); l.w = tf32_rna(v.w - h.w);
            int off = trow * SA_PAD + q * 4;
            *(float4*)(sAh + off) = h;
            *(float4*)(sAl + off) = l;
        }

        // issue next B + prefetch next A while chunk c computes
        if (c + 1 < nChunks) {
            issue_B(c + 1, buf ^ 1);
            load_A(c + 1, vb);
            CP_WAIT(1);
        } else {
            CP_WAIT(0);
        }
        __syncthreads();

        const float* sBh = sB + buf * 2 * SB_ELEMS;
        const float* sBl = sBh + SB_ELEMS;

#pragma unroll
        for (int ks = 0; ks < 4; ks++) {
            int k0 = ks << 3;
            uint32_t aH[2][4], aL[2][4];
#pragma unroll
            for (int mt = 0; mt < 2; mt++) {
                int m0 = (wm << 5) + (mt << 4) + gi;
                int base0 = m0 * SA_PAD + k0 + tg;
                int base1 = (m0 + 8) * SA_PAD + k0 + tg;
                aH[mt][0] = __float_as_uint(sAh[base0]);
                aH[mt][1] = __float_as_uint(sAh[base1]);
                aH[mt][2] = __float_as_uint(sAh[base0 + 4]);
                aH[mt][3] = __float_as_uint(sAh[base1 + 4]);
                aL[mt][0] = __float_as_uint(sAl[base0]);
                aL[mt][1] = __float_as_uint(sAl[base1]);
                aL[mt][2] = __float_as_uint(sAl[base0 + 4]);
                aL[mt][3] = __float_as_uint(sAl[base1 + 4]);
            }
#pragma unroll
            for (int nt = 0; nt < 8; nt++) {
                int bn = (wn << 6) + (nt << 3) + gi;
                int kb0 = (k0 + tg) * SB_PAD + bn;
                int kb1 = (k0 + tg + 4) * SB_PAD + bn;
                uint32_t bH0 = __float_as_uint(sBh[kb0]);
                uint32_t bH1 = __float_as_uint(sBh[kb1]);
                uint32_t bL0 = __float_as_uint(sBl[kb0]);
                uint32_t bL1 = __float_as_uint(sBl[kb1]);
#pragma unroll
                for (int mt = 0; mt < 2; mt++) {
                    mma_tf32(acc[mt][nt], aH[mt][0], aH[mt][1], aH[mt][2], aH[mt][3], bH0, bH1);
                    mma_tf32(acc[mt][nt], aH[mt][0], aH[mt][1], aH[mt][2], aH[mt][3], bL0, bL1);
                    mma_tf32(acc[mt][nt], aL[mt][0], aL[mt][1], aL[mt][2], aL[mt][3], bH0, bH1);
                }
            }
        }
        __syncthreads();

#pragma unroll
        for (int j = 0; j < 4; j++) va[j] = vb[j];
    }

    // --- epilogue ---
#pragma unroll
    for (int mt = 0; mt < 2; mt++) {
        int r0 = row0 + (wm << 5) + (mt << 4) + gi;
        int r1 = r0 + 8;
#pragma unroll
        for (int nt = 0; nt < 8; nt++) {
            int cc = (wn << 6) + (nt << 3) + (tg << 1);
            float b0 = bias[cc], b1 = bias[cc + 1];
            float2 o0, o1;
            o0.x = acc[mt][nt][0] + b0; o0.y = acc[mt][nt][1] + b1;
            o1.x = acc[mt][nt][2] + b0; o1.y = acc[mt][nt][3] + b1;
            if (do_relu) {
                o0.x = fmaxf(o0.x, 0.f); o0.y = fmaxf(o0.y, 0.f);
                o1.x = fmaxf(o1.x, 0.f); o1.y = fmaxf(o1.y, 0.f);
            }
            if (r0 < M) *(float2*)&out[(size_t)r0 * CDIM + cc] = o0;
            if (r1 < M) *(float2*)&out[(size_t)r1 * CDIM + cc] = o1;
        }
    }
}

// ---------------------------------------------------------------------------
// classifier: out[e] = dot(h[head[e]], h[tail[e]]) — 2 edges per warp iter
// ---------------------------------------------------------------------------
__global__ void classify_kernel(const float* __restrict__ h,
                                const int* __restrict__ head,
                                const int* __restrict__ tail,
                                float* __restrict__ out, int EL) {
    int gtid = blockIdx.x * blockDim.x + threadIdx.x;
    int warp = gtid >> 5;
    int lane = threadIdx.x & 31;
    int nwarps = (gridDim.x * blockDim.x) >> 5;
    for (int e = warp * 2; e < EL; e += nwarps * 2) {
        int a0 = head[e];
        int b0 = tail[e];
        float4 va0 = ((const float4*)(h + (size_t)a0 * CDIM))[lane];
        float4 vb0 = ((const float4*)(h + (size_t)b0 * CDIM))[lane];
        bool has1 = (e + 1 < EL);
        float4 va1, vb1;
        if (has1) {
            int a1 = head[e + 1];
            int b1 = tail[e + 1];
            va1 = ((const float4*)(h + (size_t)a1 * CDIM))[lane];
            vb1 = ((const float4*)(h + (size_t)b1 * CDIM))[lane];
        }
        float s0 = va0.x * vb0.x + va0.y * vb0.y + va0.z * vb0.z + va0.w * vb0.w;
#pragma unroll
        for (int o = 16; o; o >>= 1) s0 += __shfl_xor_sync(0xffffffffu, s0, o);
        if (lane == 0) out[e] = s0;
        if (has1) {
            float s1 = va1.x * vb1.x + va1.y * vb1.y + va1.z * vb1.z + va1.w * vb1.w;
#pragma unroll
            for (int o = 16; o; o >>= 1) s1 += __shfl_xor_sync(0xffffffffu, s1, o);
            if (lane == 0) out[e + 1] = s1;
        }
    }
}

// ---------------------------------------------------------------------------
// launch  (order arranged so gemm3t(lin) is the 5th launch -> ncu window)
// ---------------------------------------------------------------------------
extern "C" void kernel_launch(void* const* d_in, const int* in_sizes, int n_in,
                              void* d_out, int out_size) {
    const float* x      = (const float*)d_in[0];
    const int*   ei     = (const int*)d_in[1];
    const int*   eli    = (const int*)d_in[2];
    const float* W_lin  = (const float*)d_in[3];
    const float* b_lin  = (const float*)d_in[4];
    const float* W1l    = (const float*)d_in[5];
    const float* b1     = (const float*)d_in[6];
    const float* W1r    = (const float*)d_in[7];
    const float* W2l    = (const float*)d_in[8];
    const float* b2     = (const float*)d_in[9];
    const float* W2r    = (const float*)d_in[10];
    float* out = (float*)d_out;

    int E  = in_sizes[1] / 2;
    int EL = in_sizes[2] / 2;
    const int* src = ei;
    const int* dst = ei + E;
    const int* head = eli;
    const int* tail = eli + EL;

    float *h0, *agg, *h1, *wth, *wtl;
    int *cnt, *rowptr, *cursor, *esrc;
    cudaGetSymbolAddress((void**)&h0, g_h0);
    cudaGetSymbolAddress((void**)&agg, g_agg);
    cudaGetSymbolAddress((void**)&h1, g_h1);
    cudaGetSymbolAddress((void**)&cnt, g_cnt);
    cudaGetSymbolAddress((void**)&rowptr, g_rowptr);
    cudaGetSymbolAddress((void**)&cursor, g_cursor);
    cudaGetSymbolAddress((void**)&esrc, g_esrc);
    cudaGetSymbolAddress((void**)&wth, g_wt_hi);
    cudaGetSymbolAddress((void**)&wtl, g_wt_lo);

    cudaFuncSetAttribute(gemm3t_kernel, cudaFuncAttributeMaxDynamicSharedMemorySize, GEMM_SMEM);

    const int M = N_NODES;
    const int gemm_blocks = (M + 127) / 128;      // 391
    const int agg_blocks = (M * 32 + 255) / 256;

    // (1) memset, (2) hist, (3) scan, (4) wsplit, (5) gemm-lin <- ncu slot
    cudaMemsetAsync(cnt, 0, M * sizeof(int));
    hist_kernel<<<1024, 256>>>(dst, cnt, E);
    scan_kernel<<<1, 1024>>>(cnt, rowptr, cursor, M);
    wsplit_all_kernel<<<(WT_TOTAL + 255) / 256, 256>>>(W_lin, W1l, W1r, W2l, W2r, wth, wtl);

    // ---- h0 = x @ W_lin + b_lin ----
    gemm3t_kernel<<<gemm_blocks, 256, GEMM_SMEM>>>(
        x, XDIM, (const float*)nullptr, 0,
        wth + WT_OFF_LIN, wtl + WT_OFF_LIN, (const float*)nullptr, (const float*)nullptr,
        b_lin, h0, M, 0);

    // CSR fill (needed only before aggregation)
    fill_kernel<<<1024, 256>>>(src, dst, cursor, esrc, E);

    // ---- layer 1 ----
    aggregate_kernel<<<agg_blocks, 256>>>(h0, rowptr, esrc, agg, M);
    gemm3t_kernel<<<gemm_blocks, 256, GEMM_SMEM>>>(
        agg, CDIM, h0, CDIM,
        wth + WT_OFF_1L, wtl + WT_OFF_1L, wth + WT_OFF_1R, wtl + WT_OFF_1R,
        b1, h1, M, 1);

    // ---- layer 2 ----
    aggregate_kernel<<<agg_blocks, 256>>>(h1, rowptr, esrc, agg, M);
    gemm3t_kernel<<<gemm_blocks, 256, GEMM_SMEM>>>(
        agg, CDIM, h1, CDIM,
        wth + WT_OFF_2L, wtl + WT_OFF_2L, wth + WT_OFF_2R, wtl + WT_OFF_2R,
        b2, h0, M, 0);

    // ---- classifier ----
    classify_kernel<<<4096, 256>>>(h0, head, tail, out, EL);
}

// round 10
// speedup vs baseline: 1.2928x; 1.2928x over previous
#include <cuda_runtime.h>
#include <cuda_bf16.h>
#include <cstdint>

#define N_NODES 50000
#define CDIM 128
#define XDIM 384
#define E_MAX 1000000

// ---------------------------------------------------------------------------
// scratch (__device__ globals; no allocation allowed)
// ---------------------------------------------------------------------------
__device__ float g_h0[N_NODES * CDIM];
__device__ float g_agg[N_NODES * CDIM];
__device__ float g_h1[N_NODES * CDIM];
__device__ int   g_cnt[N_NODES];
__device__ int   g_rowptr[N_NODES + 1];
__device__ int   g_cursor[N_NODES];
__device__ int   g_esrc[E_MAX];

// bf16-split packed weights: word p = {lo16: bf16 W[2kp][n], hi16: bf16 W[2kp+1][n]}
// layout per matrix: [K/2][128] uint32, matrices concatenated
#define WT_OFF_LIN 0
#define WT_OFF_1L  (XDIM * CDIM)
#define WT_OFF_1R  (WT_OFF_1L + CDIM * CDIM)
#define WT_OFF_2L  (WT_OFF_1R + CDIM * CDIM)
#define WT_OFF_2R  (WT_OFF_2L + CDIM * CDIM)
#define WT_TOTAL   (WT_OFF_2R + CDIM * CDIM)
#define WP_OFF_LIN (WT_OFF_LIN / 2)
#define WP_OFF_1L  (WT_OFF_1L / 2)
#define WP_OFF_1R  (WT_OFF_1R / 2)
#define WP_OFF_2L  (WT_OFF_2L / 2)
#define WP_OFF_2R  (WT_OFF_2R / 2)
#define WP_TOTAL   (WT_TOTAL / 2)
__device__ uint32_t g_wbh[WP_TOTAL];
__device__ uint32_t g_wbl[WP_TOTAL];

// ---------------------------------------------------------------------------
// helpers
// ---------------------------------------------------------------------------
__device__ __forceinline__ float bf16_rn_f(float x) {
    __nv_bfloat16 b = __float2bfloat16_rn(x);
    return __bfloat162float(b);
}
// pack two floats as bf16x2: low half = e, high half = o
__device__ __forceinline__ uint32_t pack2bf(float e, float o) {
    uint32_t r;
    asm("cvt.rn.bf16x2.f32 %0, %1, %2;" : "=r"(r) : "f"(o), "f"(e));
    return r;
}

__device__ __forceinline__ uint32_t smem_u32(const void* p) {
    uint32_t a;
    asm("{ .reg .u64 t; cvta.to.shared.u64 t, %1; cvt.u32.u64 %0, t; }" : "=r"(a) : "l"(p));
    return a;
}

__device__ __forceinline__ void cp_async16(uint32_t smem_addr, const void* gptr) {
    asm volatile("cp.async.cg.shared.global [%0], [%1], 16;" :: "r"(smem_addr), "l"(gptr));
}
#define CP_COMMIT() asm volatile("cp.async.commit_group;" ::: "memory")
#define CP_WAIT(n)  asm volatile("cp.async.wait_group %0;" :: "n"(n) : "memory")

__device__ __forceinline__ void mma_bf16(float* d,
                                         uint32_t a0, uint32_t a1, uint32_t a2, uint32_t a3,
                                         uint32_t b0, uint32_t b1) {
    asm volatile(
        "mma.sync.aligned.m16n8k16.row.col.f32.bf16.bf16.f32 "
        "{%0,%1,%2,%3}, {%4,%5,%6,%7}, {%8,%9}, {%0,%1,%2,%3};"
        : "+f"(d[0]), "+f"(d[1]), "+f"(d[2]), "+f"(d[3])
        : "r"(a0), "r"(a1), "r"(a2), "r"(a3), "r"(b0), "r"(b1));
}

// ---------------------------------------------------------------------------
// CSR build
// ---------------------------------------------------------------------------
__global__ void hist_kernel(const int* __restrict__ dst, int* __restrict__ cnt, int E) {
    int i = blockIdx.x * blockDim.x + threadIdx.x;
    int stride = gridDim.x * blockDim.x;
    for (; i < E; i += stride) atomicAdd(&cnt[dst[i]], 1);
}

__global__ void scan_kernel(const int* __restrict__ cnt, int* __restrict__ rowptr,
                            int* __restrict__ cursor, int n) {
    __shared__ int wsum[32];
    __shared__ int carry;
    int tid = threadIdx.x, lane = tid & 31, wid = tid >> 5;
    if (tid == 0) carry = 0;
    __syncthreads();
    for (int base = 0; base < n; base += 1024) {
        int idx = base + tid;
        int v = (idx < n) ? cnt[idx] : 0;
        int x = v;
#pragma unroll
        for (int off = 1; off < 32; off <<= 1) {
            int t = __shfl_up_sync(0xffffffffu, x, off);
            if (lane >= off) x += t;
        }
        if (lane == 31) wsum[wid] = x;
        __syncthreads();
        if (wid == 0) {
            int w = wsum[lane];
#pragma unroll
            for (int off = 1; off < 32; off <<= 1) {
                int t = __shfl_up_sync(0xffffffffu, w, off);
                if (lane >= off) w += t;
            }
            wsum[lane] = w;
        }
        __syncthreads();
        int incl = x + (wid ? wsum[wid - 1] : 0);
        int excl = incl - v + carry;
        if (idx < n) { rowptr[idx] = excl; cursor[idx] = excl; }
        int chunk_total = wsum[31];
        __syncthreads();
        if (tid == 0) carry += chunk_total;
        __syncthreads();
    }
    if (tid == 0) rowptr[n] = carry;
}

__global__ void fill_kernel(const int* __restrict__ src, const int* __restrict__ dst,
                            int* __restrict__ cursor, int* __restrict__ esrc, int E) {
    int i = blockIdx.x * blockDim.x + threadIdx.x;
    int stride = gridDim.x * blockDim.x;
    for (; i < E; i += stride) {
        int d = dst[i];
        int pos = atomicAdd(&cursor[d], 1);
        esrc[pos] = src[i];
    }
}

// ---------------------------------------------------------------------------
// aggregate (mean of in-neighbors): one warp per node, 4-deep unroll
// ---------------------------------------------------------------------------
__global__ void aggregate_kernel(const float* __restrict__ h,
                                 const int* __restrict__ rowptr,
                                 const int* __restrict__ esrc,
                                 float* __restrict__ agg, int M) {
    int warp = (blockIdx.x * blockDim.x + threadIdx.x) >> 5;
    int lane = threadIdx.x & 31;
    if (warp >= M) return;
    int beg = rowptr[warp];
    int end = rowptr[warp + 1];
    float4 a0 = make_float4(0.f, 0.f, 0.f, 0.f);
    float4 a1 = make_float4(0.f, 0.f, 0.f, 0.f);
    float4 a2 = make_float4(0.f, 0.f, 0.f, 0.f);
    float4 a3 = make_float4(0.f, 0.f, 0.f, 0.f);
    int i = beg;
    for (; i + 3 < end; i += 4) {
        int s0 = esrc[i], s1 = esrc[i + 1], s2 = esrc[i + 2], s3 = esrc[i + 3];
        float4 v0 = ((const float4*)(h + (size_t)s0 * CDIM))[lane];
        float4 v1 = ((const float4*)(h + (size_t)s1 * CDIM))[lane];
        float4 v2 = ((const float4*)(h + (size_t)s2 * CDIM))[lane];
        float4 v3 = ((const float4*)(h + (size_t)s3 * CDIM))[lane];
        a0.x += v0.x; a0.y += v0.y; a0.z += v0.z; a0.w += v0.w;
        a1.x += v1.x; a1.y += v1.y; a1.z += v1.z; a1.w += v1.w;
        a2.x += v2.x; a2.y += v2.y; a2.z += v2.z; a2.w += v2.w;
        a3.x += v3.x; a3.y += v3.y; a3.z += v3.z; a3.w += v3.w;
    }
    for (; i < end; i++) {
        int s0 = esrc[i];
        float4 v0 = ((const float4*)(h + (size_t)s0 * CDIM))[lane];
        a0.x += v0.x; a0.y += v0.y; a0.z += v0.z; a0.w += v0.w;
    }
    float inv = 1.0f / fmaxf((float)(end - beg), 1.0f);
    float4 r;
    r.x = (a0.x + a1.x + a2.x + a3.x) * inv;
    r.y = (a0.y + a1.y + a2.y + a3.y) * inv;
    r.z = (a0.z + a1.z + a2.z + a3.z) * inv;
    r.w = (a0.w + a1.w + a2.w + a3.w) * inv;
    ((float4*)(agg + (size_t)warp * CDIM))[lane] = r;
}

// ---------------------------------------------------------------------------
// weight split+pack (all 5 matrices, one launch): W[K,128] fp32 ->
// packed bf16x2 hi/lo words: word(kp,n) = {W[2kp][n], W[2kp+1][n]}
// ---------------------------------------------------------------------------
__global__ void wsplit_all_kernel(const float* __restrict__ Wlin,
                                  const float* __restrict__ W1l,
                                  const float* __restrict__ W1r,
                                  const float* __restrict__ W2l,
                                  const float* __restrict__ W2r,
                                  uint32_t* __restrict__ Th, uint32_t* __restrict__ Tl) {
    int p = blockIdx.x * blockDim.x + threadIdx.x;
    if (p >= WP_TOTAL) return;
    const float* W;
    int local;
    if (p < WP_OFF_1L)      { W = Wlin; local = p - WP_OFF_LIN; }
    else if (p < WP_OFF_1R) { W = W1l;  local = p - WP_OFF_1L; }
    else if (p < WP_OFF_2L) { W = W1r;  local = p - WP_OFF_1R; }
    else if (p < WP_OFF_2R) { W = W2l;  local = p - WP_OFF_2L; }
    else                    { W = W2r;  local = p - WP_OFF_2R; }
    int kp = local >> 7;
    int n = local & 127;
    float e = W[(size_t)(2 * kp) * CDIM + n];
    float o = W[(size_t)(2 * kp + 1) * CDIM + n];
    float he = bf16_rn_f(e);
    float ho = bf16_rn_f(o);
    Th[p] = pack2bf(he, ho);
    Tl[p] = pack2bf(e - he, o - ho);
}

// ---------------------------------------------------------------------------
// 3xBF16 mma.sync GEMM (m16n8k16), cp.async double-buffered B:
//   out[M,128] = A1[M,K1] @ B1[K1,128] + A2[M,K2] @ B2[K2,128] + bias (opt relu)
// A split to bf16 hi/lo + packed bf16x2 at staging; B pre-split/packed.
// smem (uint32 words): sAh/sAl [128][20], sB [2 stages][hi|lo][16][136]
// ---------------------------------------------------------------------------
#define SA_STRIDE 20
#define SB_STRIDE 136
#define SA_WORDS (128 * SA_STRIDE)   // 2560 per plane
#define SB_WORDS (16 * SB_STRIDE)    // 2176 per plane
#define GEMM_SMEM ((2 * SA_WORDS + 4 * SB_WORDS) * 4)  // 55296 B

__global__ __launch_bounds__(256, 2)
void gemm3b_kernel(const float* __restrict__ A1, int K1,
                   const float* __restrict__ A2, int K2,
                   const uint32_t* __restrict__ B1h, const uint32_t* __restrict__ B1l,
                   const uint32_t* __restrict__ B2h, const uint32_t* __restrict__ B2l,
                   const float* __restrict__ bias,
                   float* __restrict__ out, int M, int do_relu) {
    extern __shared__ uint32_t smw[];
    uint32_t* sAh = smw;
    uint32_t* sAl = smw + SA_WORDS;
    uint32_t* sB  = smw + 2 * SA_WORDS;   // [stage][hi/lo][SB_WORDS]

    int tid = threadIdx.x;
    int wid = tid >> 5;
    int lane = tid & 31;
    int gi = lane >> 2;
    int tg = lane & 3;
    int wm = wid & 3;
    int wn = wid >> 2;
    int row0 = blockIdx.x * 128;

    float acc[2][8][4];
#pragma unroll
    for (int mt = 0; mt < 2; mt++)
#pragma unroll
        for (int nt = 0; nt < 8; nt++)
#pragma unroll
            for (int r = 0; r < 4; r++) acc[mt][nt][r] = 0.f;

    int nChunks = (K1 + K2) >> 5;
    int trow = tid >> 1;
    int half = tid & 1;
    int arow = row0 + trow;

    auto issue_B = [&](int c, int buf) {
        int gk = c << 5;
        const uint32_t* Bh; const uint32_t* Bl; int kpb;
        if (gk < K1) { Bh = B1h; Bl = B1l; kpb = gk >> 1; }
        else         { Bh = B2h; Bl = B2l; kpb = (gk - K1) >> 1; }
        uint32_t* dsth = sB + buf * 2 * SB_WORDS;
        uint32_t* dstl = dsth + SB_WORDS;
#pragma unroll
        for (int t = 0; t < 2; t++) {
            int idx = tid + t * 256;           // 0..511 (16 rows x 32 segs)
            int kk = idx >> 5;
            int c4 = idx & 31;
            size_t goff = (size_t)(kpb + kk) * CDIM + c4 * 4;
            int soff = kk * SB_STRIDE + c4 * 4;
            cp_async16(smem_u32(dsth + soff), Bh + goff);
            cp_async16(smem_u32(dstl + soff), Bl + goff);
        }
        CP_COMMIT();
    };

    issue_B(0, 0);

    for (int c = 0; c < nChunks; c++) {
        int buf = c & 1;
        int gk = c << 5;
        const float* Asrc; int lda; int kb;
        if (gk < K1) { Asrc = A1; lda = K1; kb = gk; }
        else         { Asrc = A2; lda = K2; kb = gk - K1; }

        // --- stage A chunk: 128 rows x 32 k fp32 -> bf16 hi/lo packed pairs ---
        if (arow < M) {
            const float* ap = Asrc + (size_t)arow * lda + kb;
#pragma unroll
            for (int j = 0; j < 4; j++) {
                int q = (j << 1) | half;        // 0..7 (float4 index in k)
                float4 v = *(const float4*)(ap + q * 4);
                float hx = bf16_rn_f(v.x), hy = bf16_rn_f(v.y);
                float hz = bf16_rn_f(v.z), hw = bf16_rn_f(v.w);
                uint2 wh = make_uint2(pack2bf(hx, hy), pack2bf(hz, hw));
                uint2 wl = make_uint2(pack2bf(v.x - hx, v.y - hy),
                                      pack2bf(v.z - hz, v.w - hw));
                int off = trow * SA_STRIDE + q * 2;
                *(uint2*)(sAh + off) = wh;
                *(uint2*)(sAl + off) = wl;
            }
        } else {
            uint2 z = make_uint2(0u, 0u);
#pragma unroll
            for (int j = 0; j < 4; j++) {
                int q = (j << 1) | half;
                int off = trow * SA_STRIDE + q * 2;
                *(uint2*)(sAh + off) = z;
                *(uint2*)(sAl + off) = z;
            }
        }

        // issue next B while this chunk computes
        if (c + 1 < nChunks) {
            issue_B(c + 1, buf ^ 1);
            CP_WAIT(1);
        } else {
            CP_WAIT(0);
        }
        __syncthreads();

        const uint32_t* sBh = sB + buf * 2 * SB_WORDS;
        const uint32_t* sBl = sBh + SB_WORDS;

        // --- compute: 2 k-steps of k16 ---
#pragma unroll
        for (int ks = 0; ks < 2; ks++) {
            int kp0 = ks << 3;
            uint32_t aH[2][4], aL[2][4];
#pragma unroll
            for (int mt = 0; mt < 2; mt++) {
                int m0 = (wm << 5) + (mt << 4) + gi;
                int base0 = m0 * SA_STRIDE + kp0 + tg;
                int base1 = (m0 + 8) * SA_STRIDE + kp0 + tg;
                aH[mt][0] = sAh[base0];
                aH[mt][1] = sAh[base1];
                aH[mt][2] = sAh[base0 + 4];
                aH[mt][3] = sAh[base1 + 4];
                aL[mt][0] = sAl[base0];
                aL[mt][1] = sAl[base1];
                aL[mt][2] = sAl[base0 + 4];
                aL[mt][3] = sAl[base1 + 4];
            }
#pragma unroll
            for (int nt = 0; nt < 8; nt++) {
                int bn = (wn << 6) + (nt << 3) + gi;
                int i0 = (kp0 + tg) * SB_STRIDE + bn;
                int i1 = (kp0 + tg + 4) * SB_STRIDE + bn;
                uint32_t bH0 = sBh[i0];
                uint32_t bH1 = sBh[i1];
                uint32_t bL0 = sBl[i0];
                uint32_t bL1 = sBl[i1];
#pragma unroll
                for (int mt = 0; mt < 2; mt++) {
                    mma_bf16(acc[mt][nt], aH[mt][0], aH[mt][1], aH[mt][2], aH[mt][3], bH0, bH1);
                    mma_bf16(acc[mt][nt], aH[mt][0], aH[mt][1], aH[mt][2], aH[mt][3], bL0, bL1);
                    mma_bf16(acc[mt][nt], aL[mt][0], aL[mt][1], aL[mt][2], aL[mt][3], bH0, bH1);
                }
            }
        }
        __syncthreads();
    }

    // --- epilogue: direct STG, bias + optional relu ---
#pragma unroll
    for (int mt = 0; mt < 2; mt++) {
        int r0 = row0 + (wm << 5) + (mt << 4) + gi;
        int r1 = r0 + 8;
#pragma unroll
        for (int nt = 0; nt < 8; nt++) {
            int cc = (wn << 6) + (nt << 3) + (tg << 1);
            float b0 = bias[cc], b1 = bias[cc + 1];
            float2 o0, o1;
            o0.x = acc[mt][nt][0] + b0; o0.y = acc[mt][nt][1] + b1;
            o1.x = acc[mt][nt][2] + b0; o1.y = acc[mt][nt][3] + b1;
            if (do_relu) {
                o0.x = fmaxf(o0.x, 0.f); o0.y = fmaxf(o0.y, 0.f);
                o1.x = fmaxf(o1.x, 0.f); o1.y = fmaxf(o1.y, 0.f);
            }
            if (r0 < M) *(float2*)&out[(size_t)r0 * CDIM + cc] = o0;
            if (r1 < M) *(float2*)&out[(size_t)r1 * CDIM + cc] = o1;
        }
    }
}

// ---------------------------------------------------------------------------
// classifier: out[e] = dot(h[head[e]], h[tail[e]]) — 2 edges per warp iter
// ---------------------------------------------------------------------------
__global__ void classify_kernel(const float* __restrict__ h,
                                const int* __restrict__ head,
                                const int* __restrict__ tail,
                                float* __restrict__ out, int EL) {
    int gtid = blockIdx.x * blockDim.x + threadIdx.x;
    int warp = gtid >> 5;
    int lane = threadIdx.x & 31;
    int nwarps = (gridDim.x * blockDim.x) >> 5;
    for (int e = warp * 2; e < EL; e += nwarps * 2) {
        int a0 = head[e];
        int b0 = tail[e];
        float4 va0 = ((const float4*)(h + (size_t)a0 * CDIM))[lane];
        float4 vb0 = ((const float4*)(h + (size_t)b0 * CDIM))[lane];
        bool has1 = (e + 1 < EL);
        float4 va1, vb1;
        if (has1) {
            int a1 = head[e + 1];
            int b1 = tail[e + 1];
            va1 = ((const float4*)(h + (size_t)a1 * CDIM))[lane];
            vb1 = ((const float4*)(h + (size_t)b1 * CDIM))[lane];
        }
        float s0 = va0.x * vb0.x + va0.y * vb0.y + va0.z * vb0.z + va0.w * vb0.w;
#pragma unroll
        for (int o = 16; o; o >>= 1) s0 += __shfl_xor_sync(0xffffffffu, s0, o);
        if (lane == 0) out[e] = s0;
        if (has1) {
            float s1 = va1.x * vb1.x + va1.y * vb1.y + va1.z * vb1.z + va1.w * vb1.w;
#pragma unroll
            for (int o = 16; o; o >>= 1) s1 += __shfl_xor_sync(0xffffffffu, s1, o);
            if (lane == 0) out[e + 1] = s1;
        }
    }
}

// ---------------------------------------------------------------------------
// launch  (gemm3b(lin) kept in the 5th launch slot for ncu)
// ---------------------------------------------------------------------------
extern "C" void kernel_launch(void* const* d_in, const int* in_sizes, int n_in,
                              void* d_out, int out_size) {
    const float* x      = (const float*)d_in[0];
    const int*   ei     = (const int*)d_in[1];
    const int*   eli    = (const int*)d_in[2];
    const float* W_lin  = (const float*)d_in[3];
    const float* b_lin  = (const float*)d_in[4];
    const float* W1l    = (const float*)d_in[5];
    const float* b1     = (const float*)d_in[6];
    const float* W1r    = (const float*)d_in[7];
    const float* W2l    = (const float*)d_in[8];
    const float* b2     = (const float*)d_in[9];
    const float* W2r    = (const float*)d_in[10];
    float* out = (float*)d_out;

    int E  = in_sizes[1] / 2;
    int EL = in_sizes[2] / 2;
    const int* src = ei;
    const int* dst = ei + E;
    const int* head = eli;
    const int* tail = eli + EL;

    float *h0, *agg, *h1;
    uint32_t *wbh, *wbl;
    int *cnt, *rowptr, *cursor, *esrc;
    cudaGetSymbolAddress((void**)&h0, g_h0);
    cudaGetSymbolAddress((void**)&agg, g_agg);
    cudaGetSymbolAddress((void**)&h1, g_h1);
    cudaGetSymbolAddress((void**)&cnt, g_cnt);
    cudaGetSymbolAddress((void**)&rowptr, g_rowptr);
    cudaGetSymbolAddress((void**)&cursor, g_cursor);
    cudaGetSymbolAddress((void**)&esrc, g_esrc);
    cudaGetSymbolAddress((void**)&wbh, g_wbh);
    cudaGetSymbolAddress((void**)&wbl, g_wbl);

    cudaFuncSetAttribute(gemm3b_kernel, cudaFuncAttributeMaxDynamicSharedMemorySize, GEMM_SMEM);

    const int M = N_NODES;
    const int gemm_blocks = (M + 127) / 128;      // 391
    const int agg_blocks = (M * 32 + 255) / 256;

    // (1) memset, (2) hist, (3) scan, (4) wsplit, (5) gemm-lin <- ncu slot
    cudaMemsetAsync(cnt, 0, M * sizeof(int));
    hist_kernel<<<1024, 256>>>(dst, cnt, E);
    scan_kernel<<<1, 1024>>>(cnt, rowptr, cursor, M);
    wsplit_all_kernel<<<(WP_TOTAL + 255) / 256, 256>>>(W_lin, W1l, W1r, W2l, W2r, wbh, wbl);

    // ---- h0 = x @ W_lin + b_lin ----
    gemm3b_kernel<<<gemm_blocks, 256, GEMM_SMEM>>>(
        x, XDIM, (const float*)nullptr, 0,
        wbh + WP_OFF_LIN, wbl + WP_OFF_LIN, (const uint32_t*)nullptr, (const uint32_t*)nullptr,
        b_lin, h0, M, 0);

    // CSR fill (needed only before aggregation)
    fill_kernel<<<1024, 256>>>(src, dst, cursor, esrc, E);

    // ---- layer 1 ----
    aggregate_kernel<<<agg_blocks, 256>>>(h0, rowptr, esrc, agg, M);
    gemm3b_kernel<<<gemm_blocks, 256, GEMM_SMEM>>>(
        agg, CDIM, h0, CDIM,
        wbh + WP_OFF_1L, wbl + WP_OFF_1L, wbh + WP_OFF_1R, wbl + WP_OFF_1R,
        b1, h1, M, 1);

    // ---- layer 2 ----
    aggregate_kernel<<<agg_blocks, 256>>>(h1, rowptr, esrc, agg, M);
    gemm3b_kernel<<<gemm_blocks, 256, GEMM_SMEM>>>(
        agg, CDIM, h1, CDIM,
        wbh + WP_OFF_2L, wbl + WP_OFF_2L, wbh + WP_OFF_2R, wbl + WP_OFF_2R,
        b2, h0, M, 0);

    // ---- classifier ----
    classify_kernel<<<4096, 256>>>(h0, head, tail, out, EL);
}